// round 1
// baseline (speedup 1.0000x reference)
#include <cuda_runtime.h>
#include <math.h>

#define Bb 16
#define II 512
#define HH 1024
#define BH (Bb*HH)            // 16384
#define BHI (Bb*HH*II)        // 8388608
#define BHH (Bb*HH*HH)        // 16777216

// Output offsets (floats) in order: h, c, e_w_ix, e_w_ih, e_b_i, e_w_fx, e_w_fh, e_b_f, e_w_cx, e_w_ch, e_b_c
#define OFF_H     0
#define OFF_C     16384
#define OFF_EWIX  32768
#define OFF_EWIH  8421376
#define OFF_EBI   25198592
#define OFF_EWFX  25214976
#define OFF_EWFH  33603584
#define OFF_EBF   50380800
#define OFF_EWCX  50397184
#define OFF_EWCH  58785792
#define OFF_EBC   75563008

// Scratch (no allocation allowed)
__device__ float  g_gates[4 * BH];   // i, f, o, c_hat
__device__ float4 g_coef[BH];        // (f, a_i, a_f, a_c)

struct GatePtrs {
    const float* wx[4];
    const float* wh[4];
    const float* bias[4];
};

// ---------------------------------------------------------------------------
// Kernel 1: gate pre-activations + activation.
// grid = (HH/32, 4 gates), block = 256. Each warp computes 4 consecutive j
// rows for all 16 batches (weight element loaded once, 16 FMAs reuse).
// x and h_last for ALL batches staged in 96KB dynamic shared memory.
// ---------------------------------------------------------------------------
__global__ __launch_bounds__(256) void gates_kernel(
    const float* __restrict__ x, const float* __restrict__ h_last, GatePtrs p)
{
    extern __shared__ float smem[];
    float* sx = smem;            // Bb*II = 8192 floats (32KB)
    float* sh = smem + Bb * II;  // Bb*HH = 16384 floats (64KB)

    int tid = threadIdx.x;
    for (int t = tid; t < (Bb * II) / 4; t += 256)
        ((float4*)sx)[t] = ((const float4*)x)[t];
    for (int t = tid; t < (Bb * HH) / 4; t += 256)
        ((float4*)sh)[t] = ((const float4*)h_last)[t];
    __syncthreads();

    const int g    = blockIdx.y;
    const int warp = tid >> 5;
    const int lane = tid & 31;
    const int j0   = blockIdx.x * 32 + warp * 4;

    float acc[4][Bb];
#pragma unroll
    for (int jj = 0; jj < 4; jj++)
#pragma unroll
        for (int b = 0; b < Bb; b++) acc[jj][b] = 0.f;

    // x @ Wx^T part
    {
        const float* wx = p.wx[g] + (size_t)j0 * II;
        for (int k = lane; k < II; k += 32) {
            float w0 = wx[k], w1 = wx[II + k], w2 = wx[2 * II + k], w3 = wx[3 * II + k];
#pragma unroll
            for (int b = 0; b < Bb; b++) {
                float xv = sx[b * II + k];
                acc[0][b] = fmaf(w0, xv, acc[0][b]);
                acc[1][b] = fmaf(w1, xv, acc[1][b]);
                acc[2][b] = fmaf(w2, xv, acc[2][b]);
                acc[3][b] = fmaf(w3, xv, acc[3][b]);
            }
        }
    }
    // h_last @ Wh^T part
    {
        const float* wh = p.wh[g] + (size_t)j0 * HH;
        for (int k = lane; k < HH; k += 32) {
            float w0 = wh[k], w1 = wh[HH + k], w2 = wh[2 * HH + k], w3 = wh[3 * HH + k];
#pragma unroll
            for (int b = 0; b < Bb; b++) {
                float hv = sh[b * HH + k];
                acc[0][b] = fmaf(w0, hv, acc[0][b]);
                acc[1][b] = fmaf(w1, hv, acc[1][b]);
                acc[2][b] = fmaf(w2, hv, acc[2][b]);
                acc[3][b] = fmaf(w3, hv, acc[3][b]);
            }
        }
    }

    // warp tree-reduce all 64 accumulators
#pragma unroll
    for (int off = 16; off; off >>= 1)
#pragma unroll
        for (int jj = 0; jj < 4; jj++)
#pragma unroll
            for (int b = 0; b < Bb; b++)
                acc[jj][b] += __shfl_xor_sync(0xffffffffu, acc[jj][b], off);

    if (lane == 0) {
#pragma unroll
        for (int jj = 0; jj < 4; jj++) {
            float bias = p.bias[g][j0 + jj];
#pragma unroll
            for (int b = 0; b < Bb; b++) {
                float z = acc[jj][b] + bias;
                float v = (g == 3) ? tanhf(z) : 1.f / (1.f + expf(-z));
                g_gates[g * BH + b * HH + j0 + jj] = v;
            }
        }
    }
}

// ---------------------------------------------------------------------------
// Kernel 2: pointwise. h, c, e_b outputs + coefficient pack for kernel 3.
// ---------------------------------------------------------------------------
__global__ __launch_bounds__(256) void point_kernel(
    const float* __restrict__ c_last,
    const float* __restrict__ eb_i, const float* __restrict__ eb_f,
    const float* __restrict__ eb_c, float* __restrict__ out)
{
    int idx = blockIdx.x * 256 + threadIdx.x;   // < BH
    float i  = g_gates[idx];
    float f  = g_gates[BH + idx];
    float o  = g_gates[2 * BH + idx];
    float ch = g_gates[3 * BH + idx];
    float cl = c_last[idx];

    float c = fmaf(f, cl, i * ch);
    float h = o * c;
    float di  = i * (1.f - i);
    float df  = f * (1.f - f);
    float dch = 1.f - ch * ch;
    float ai = di * ch;     // also delta for e_b_i
    float af = df * cl;     // delta for e_b_f
    float ac = dch * i;     // delta for e_b_c

    out[OFF_H + idx] = h;
    out[OFF_C + idx] = c;
    out[OFF_EBI + idx] = fmaf(eb_i[idx], f, ai);
    out[OFF_EBF + idx] = fmaf(eb_f[idx], f, af);
    out[OFF_EBC + idx] = fmaf(eb_c[idx], f, ac);
    g_coef[idx] = make_float4(f, ai, af, ac);
}

// ---------------------------------------------------------------------------
// Kernel 3: the HBM-bound trace update. grid = (HH/JT, Bb), block = 256.
// Each block: one batch b, JT rows. x[b], h_last[b] cached in SMEM.
// new_e[b,j,k] = e[b,j,k]*f[b,j] + a[b,j]*v[b,k], float4 streaming.
// ---------------------------------------------------------------------------
#define JT 8

__global__ __launch_bounds__(256) void trace_kernel(
    const float* __restrict__ x, const float* __restrict__ h_last,
    const float* __restrict__ e_ix, const float* __restrict__ e_ih,
    const float* __restrict__ e_fx, const float* __restrict__ e_fh,
    const float* __restrict__ e_cx, const float* __restrict__ e_ch,
    float* __restrict__ out)
{
    __shared__ float4 sx[II / 4];   // 2KB
    __shared__ float4 sh[HH / 4];   // 4KB
    __shared__ float4 scf[JT];

    const int tid = threadIdx.x;
    const int b   = blockIdx.y;
    const int j0  = blockIdx.x * JT;

    for (int t = tid; t < II / 4; t += 256) sx[t] = ((const float4*)(x + b * II))[t];
    for (int t = tid; t < HH / 4; t += 256) sh[t] = ((const float4*)(h_last + b * HH))[t];
    if (tid < JT) scf[tid] = g_coef[b * HH + j0 + tid];
    __syncthreads();

    const size_t baseH = (size_t)(b * HH + j0) * (HH / 4);
    const size_t baseI = (size_t)(b * HH + j0) * (II / 4);

#define TRACE_H(SRC, OFF, SEL)                                              \
    {                                                                       \
        const float4* ein = (const float4*)(SRC) + baseH;                   \
        float4* eo = (float4*)(out + (OFF)) + baseH;                        \
        _Pragma("unroll 8")                                                 \
        for (int t = tid; t < JT * (HH / 4); t += 256) {                    \
            float4 cf = scf[t >> 8];                                        \
            float fv = cf.x, a = cf.SEL;                                    \
            float4 e  = __ldcs(ein + t);                                    \
            float4 hv = sh[t & 255];                                        \
            float4 r;                                                       \
            r.x = fmaf(e.x, fv, a * hv.x);                                  \
            r.y = fmaf(e.y, fv, a * hv.y);                                  \
            r.z = fmaf(e.z, fv, a * hv.z);                                  \
            r.w = fmaf(e.w, fv, a * hv.w);                                  \
            __stcs(eo + t, r);                                              \
        }                                                                   \
    }

#define TRACE_X(SRC, OFF, SEL)                                              \
    {                                                                       \
        const float4* ein = (const float4*)(SRC) + baseI;                   \
        float4* eo = (float4*)(out + (OFF)) + baseI;                        \
        _Pragma("unroll 4")                                                 \
        for (int t = tid; t < JT * (II / 4); t += 256) {                    \
            float4 cf = scf[t >> 7];                                        \
            float fv = cf.x, a = cf.SEL;                                    \
            float4 e  = __ldcs(ein + t);                                    \
            float4 xv = sx[t & 127];                                        \
            float4 r;                                                       \
            r.x = fmaf(e.x, fv, a * xv.x);                                  \
            r.y = fmaf(e.y, fv, a * xv.y);                                  \
            r.z = fmaf(e.z, fv, a * xv.z);                                  \
            r.w = fmaf(e.w, fv, a * xv.w);                                  \
            __stcs(eo + t, r);                                              \
        }                                                                   \
    }

    TRACE_H(e_ih, OFF_EWIH, y)
    TRACE_H(e_fh, OFF_EWFH, z)
    TRACE_H(e_ch, OFF_EWCH, w)
    TRACE_X(e_ix, OFF_EWIX, y)
    TRACE_X(e_fx, OFF_EWFX, z)
    TRACE_X(e_cx, OFF_EWCX, w)
}

// ---------------------------------------------------------------------------
extern "C" void kernel_launch(void* const* d_in, const int* in_sizes, int n_in,
                              void* d_out, int out_size)
{
    const float* x      = (const float*)d_in[0];
    const float* w_ix   = (const float*)d_in[1];
    const float* w_ih   = (const float*)d_in[2];
    const float* b_i    = (const float*)d_in[3];
    const float* w_fx   = (const float*)d_in[4];
    const float* w_fh   = (const float*)d_in[5];
    const float* b_f    = (const float*)d_in[6];
    const float* w_ox   = (const float*)d_in[7];
    const float* w_oh   = (const float*)d_in[8];
    const float* b_o    = (const float*)d_in[9];
    const float* w_cx   = (const float*)d_in[10];
    const float* w_ch   = (const float*)d_in[11];
    const float* b_c    = (const float*)d_in[12];
    const float* h_last = (const float*)d_in[13];
    const float* c_last = (const float*)d_in[14];
    const float* e_w_ix = (const float*)d_in[15];
    const float* e_w_ih = (const float*)d_in[16];
    const float* e_b_i  = (const float*)d_in[17];
    const float* e_w_fx = (const float*)d_in[18];
    const float* e_w_fh = (const float*)d_in[19];
    const float* e_b_f  = (const float*)d_in[20];
    const float* e_w_cx = (const float*)d_in[21];
    const float* e_w_ch = (const float*)d_in[22];
    const float* e_b_c  = (const float*)d_in[23];
    float* out = (float*)d_out;

    GatePtrs p;
    p.wx[0] = w_ix; p.wx[1] = w_fx; p.wx[2] = w_ox; p.wx[3] = w_cx;
    p.wh[0] = w_ih; p.wh[1] = w_fh; p.wh[2] = w_oh; p.wh[3] = w_ch;
    p.bias[0] = b_i; p.bias[1] = b_f; p.bias[2] = b_o; p.bias[3] = b_c;

    const int smem1 = (Bb * II + Bb * HH) * (int)sizeof(float);  // 96KB
    cudaFuncSetAttribute(gates_kernel, cudaFuncAttributeMaxDynamicSharedMemorySize, smem1);

    dim3 g1(HH / 32, 4);
    gates_kernel<<<g1, 256, smem1>>>(x, h_last, p);

    point_kernel<<<BH / 256, 256>>>(c_last, e_b_i, e_b_f, e_b_c, out);

    dim3 g3(HH / JT, Bb);
    trace_kernel<<<g3, 256>>>(x, h_last, e_w_ix, e_w_ih, e_w_fx, e_w_fh,
                              e_w_cx, e_w_ch, out);
}

// round 2
// speedup vs baseline: 1.1246x; 1.1246x over previous
#include <cuda_runtime.h>
#include <math.h>

#define Bb 16
#define II 512
#define HH 1024
#define BH (Bb*HH)            // 16384

// Output offsets (floats): h, c, e_w_ix, e_w_ih, e_b_i, e_w_fx, e_w_fh, e_b_f, e_w_cx, e_w_ch, e_b_c
#define OFF_H     0
#define OFF_C     16384
#define OFF_EWIX  32768
#define OFF_EWIH  8421376
#define OFF_EBI   25198592
#define OFF_EWFX  25214976
#define OFF_EWFH  33603584
#define OFF_EBF   50380800
#define OFF_EWCX  50397184
#define OFF_EWCH  58785792
#define OFF_EBC   75563008

// Scratch (no allocation allowed)
__device__ float  g_part[3][4 * BH];  // partial pre-activations per K-chunk
__device__ float4 g_coef[BH];         // (f, a_i, a_f, a_c)

struct GatePtrs {
    const float* wx[4];
    const float* wh[4];
};

#define FMA4(A, Z, ACC)                         \
    ACC = fmaf((A).x, (Z).x, ACC);              \
    ACC = fmaf((A).y, (Z).y, ACC);              \
    ACC = fmaf((A).z, (Z).z, ACC);              \
    ACC = fmaf((A).w, (Z).w, ACC);

// ---------------------------------------------------------------------------
// Kernel 1: gate pre-activation partials.
// grid = (HH/16, 4 gates, 3 K-chunks), block = 128 (4 warps).
// chunk 0: x @ Wx^T (K=512); chunk 1: h[:,0:512] @ Wh[:,0:512]^T;
// chunk 2: h[:,512:1024] @ Wh[:,512:1024]^T.
// Each warp: 4 consecutive j-rows x all 16 batches (64 accumulators).
// Weights read as float4 (4 independent LDG.128 in flight per iter).
// Chunk operand (16 batches x 512 cols = 32KB) staged in static SMEM.
// ---------------------------------------------------------------------------
__global__ __launch_bounds__(128) void gates_kernel(
    const float* __restrict__ x, const float* __restrict__ h_last, GatePtrs p)
{
    __shared__ float4 sz[2048];    // 16 b * 128 float4 = 32KB

    const int tid   = threadIdx.x;
    const int chunk = blockIdx.z;
    const int g     = blockIdx.y;

    // Stage this chunk's operand: sz[b*128 + kq] = z[b][chunk_cols + kq]
    if (chunk == 0) {
        const float4* src = (const float4*)x;   // Bb*II/4 = 2048 float4
#pragma unroll
        for (int t = tid; t < 2048; t += 128) sz[t] = src[t];
    } else {
        const float4* src = (const float4*)h_last;  // rows of 256 float4
        const int off = (chunk - 1) * 128;
#pragma unroll
        for (int t = tid; t < 2048; t += 128) {
            int b = t >> 7, kq = t & 127;
            sz[t] = src[b * 256 + off + kq];
        }
    }
    __syncthreads();

    const int warp = tid >> 5;
    const int lane = tid & 31;
    const int j0   = blockIdx.x * 16 + warp * 4;

    const float* wbase;
    int rowlen, koff;
    if (chunk == 0) { wbase = p.wx[g]; rowlen = II; koff = 0; }
    else            { wbase = p.wh[g]; rowlen = HH; koff = (chunk - 1) * 512; }

    const float4* w0 = (const float4*)(wbase + (size_t)(j0 + 0) * rowlen + koff);
    const float4* w1 = (const float4*)(wbase + (size_t)(j0 + 1) * rowlen + koff);
    const float4* w2 = (const float4*)(wbase + (size_t)(j0 + 2) * rowlen + koff);
    const float4* w3 = (const float4*)(wbase + (size_t)(j0 + 3) * rowlen + koff);

    float acc[4][Bb];
#pragma unroll
    for (int jj = 0; jj < 4; jj++)
#pragma unroll
        for (int b = 0; b < Bb; b++) acc[jj][b] = 0.f;

#pragma unroll
    for (int it = 0; it < 4; it++) {
        const int k4 = it * 32 + lane;
        float4 a0 = w0[k4];
        float4 a1 = w1[k4];
        float4 a2 = w2[k4];
        float4 a3 = w3[k4];
#pragma unroll
        for (int b = 0; b < Bb; b++) {
            float4 z = sz[b * 128 + k4];
            FMA4(a0, z, acc[0][b]);
            FMA4(a1, z, acc[1][b]);
            FMA4(a2, z, acc[2][b]);
            FMA4(a3, z, acc[3][b]);
        }
    }

    // reduce 64 accumulators across the warp
#pragma unroll
    for (int off = 16; off; off >>= 1)
#pragma unroll
        for (int jj = 0; jj < 4; jj++)
#pragma unroll
            for (int b = 0; b < Bb; b++)
                acc[jj][b] += __shfl_xor_sync(0xffffffffu, acc[jj][b], off);

    if (lane == 0) {
        float* dst = g_part[chunk] + g * BH + j0;
#pragma unroll
        for (int b = 0; b < Bb; b++)
#pragma unroll
            for (int jj = 0; jj < 4; jj++)
                dst[b * HH + jj] = acc[jj][b];
    }
}

// ---------------------------------------------------------------------------
// Kernel 2: pointwise. Sum partials + bias + activation, emit h, c, e_b
// outputs and coefficient pack (f, a_i, a_f, a_c) for the trace kernel.
// ---------------------------------------------------------------------------
__global__ __launch_bounds__(256) void point_kernel(
    const float* __restrict__ c_last,
    const float* __restrict__ b_i, const float* __restrict__ b_f,
    const float* __restrict__ b_o, const float* __restrict__ b_c,
    const float* __restrict__ eb_i, const float* __restrict__ eb_f,
    const float* __restrict__ eb_c, float* __restrict__ out)
{
    const int idx = blockIdx.x * 256 + threadIdx.x;   // < BH
    const int j   = idx & (HH - 1);

    float pi = g_part[0][0 * BH + idx] + g_part[1][0 * BH + idx] + g_part[2][0 * BH + idx] + b_i[j];
    float pf = g_part[0][1 * BH + idx] + g_part[1][1 * BH + idx] + g_part[2][1 * BH + idx] + b_f[j];
    float po = g_part[0][2 * BH + idx] + g_part[1][2 * BH + idx] + g_part[2][2 * BH + idx] + b_o[j];
    float pc = g_part[0][3 * BH + idx] + g_part[1][3 * BH + idx] + g_part[2][3 * BH + idx] + b_c[j];

    float i  = 1.f / (1.f + expf(-pi));
    float f  = 1.f / (1.f + expf(-pf));
    float o  = 1.f / (1.f + expf(-po));
    float ch = tanhf(pc);
    float cl = c_last[idx];

    float c = fmaf(f, cl, i * ch);
    float h = o * c;
    float di  = i * (1.f - i);
    float df  = f * (1.f - f);
    float dch = 1.f - ch * ch;
    float ai = di * ch;
    float af = df * cl;
    float ac = dch * i;

    out[OFF_H + idx]   = h;
    out[OFF_C + idx]   = c;
    out[OFF_EBI + idx] = fmaf(eb_i[idx], f, ai);
    out[OFF_EBF + idx] = fmaf(eb_f[idx], f, af);
    out[OFF_EBC + idx] = fmaf(eb_c[idx], f, ac);
    g_coef[idx] = make_float4(f, ai, af, ac);
}

// ---------------------------------------------------------------------------
// Kernel 3: HBM-bound trace update (near roofline already).
// grid = (HH/JT, Bb), block = 256. Each block: one batch b, JT rows.
// new_e[b,j,k] = e[b,j,k]*f[b,j] + a[b,j]*v[b,k], float4 streaming.
// ---------------------------------------------------------------------------
#define JT 8

__global__ __launch_bounds__(256) void trace_kernel(
    const float* __restrict__ x, const float* __restrict__ h_last,
    const float* __restrict__ e_ix, const float* __restrict__ e_ih,
    const float* __restrict__ e_fx, const float* __restrict__ e_fh,
    const float* __restrict__ e_cx, const float* __restrict__ e_ch,
    float* __restrict__ out)
{
    __shared__ float4 sx[II / 4];   // 2KB
    __shared__ float4 sh[HH / 4];   // 4KB
    __shared__ float4 scf[JT];

    const int tid = threadIdx.x;
    const int b   = blockIdx.y;
    const int j0  = blockIdx.x * JT;

    for (int t = tid; t < II / 4; t += 256) sx[t] = ((const float4*)(x + b * II))[t];
    for (int t = tid; t < HH / 4; t += 256) sh[t] = ((const float4*)(h_last + b * HH))[t];
    if (tid < JT) scf[tid] = g_coef[b * HH + j0 + tid];
    __syncthreads();

    const size_t baseH = (size_t)(b * HH + j0) * (HH / 4);
    const size_t baseI = (size_t)(b * HH + j0) * (II / 4);

#define TRACE_H(SRC, OFF, SEL)                                              \
    {                                                                       \
        const float4* ein = (const float4*)(SRC) + baseH;                   \
        float4* eo = (float4*)(out + (OFF)) + baseH;                        \
        _Pragma("unroll 8")                                                 \
        for (int t = tid; t < JT * (HH / 4); t += 256) {                    \
            float4 cf = scf[t >> 8];                                        \
            float fv = cf.x, a = cf.SEL;                                    \
            float4 e  = __ldcs(ein + t);                                    \
            float4 hv = sh[t & 255];                                        \
            float4 r;                                                       \
            r.x = fmaf(e.x, fv, a * hv.x);                                  \
            r.y = fmaf(e.y, fv, a * hv.y);                                  \
            r.z = fmaf(e.z, fv, a * hv.z);                                  \
            r.w = fmaf(e.w, fv, a * hv.w);                                  \
            __stcs(eo + t, r);                                              \
        }                                                                   \
    }

#define TRACE_X(SRC, OFF, SEL)                                              \
    {                                                                       \
        const float4* ein = (const float4*)(SRC) + baseI;                   \
        float4* eo = (float4*)(out + (OFF)) + baseI;                        \
        _Pragma("unroll 4")                                                 \
        for (int t = tid; t < JT * (II / 4); t += 256) {                    \
            float4 cf = scf[t >> 7];                                        \
            float fv = cf.x, a = cf.SEL;                                    \
            float4 e  = __ldcs(ein + t);                                    \
            float4 xv = sx[t & 127];                                        \
            float4 r;                                                       \
            r.x = fmaf(e.x, fv, a * xv.x);                                  \
            r.y = fmaf(e.y, fv, a * xv.y);                                  \
            r.z = fmaf(e.z, fv, a * xv.z);                                  \
            r.w = fmaf(e.w, fv, a * xv.w);                                  \
            __stcs(eo + t, r);                                              \
        }                                                                   \
    }

    TRACE_H(e_ih, OFF_EWIH, y)
    TRACE_H(e_fh, OFF_EWFH, z)
    TRACE_H(e_ch, OFF_EWCH, w)
    TRACE_X(e_ix, OFF_EWIX, y)
    TRACE_X(e_fx, OFF_EWFX, z)
    TRACE_X(e_cx, OFF_EWCX, w)
}

// ---------------------------------------------------------------------------
extern "C" void kernel_launch(void* const* d_in, const int* in_sizes, int n_in,
                              void* d_out, int out_size)
{
    const float* x      = (const float*)d_in[0];
    const float* w_ix   = (const float*)d_in[1];
    const float* w_ih   = (const float*)d_in[2];
    const float* b_i    = (const float*)d_in[3];
    const float* w_fx   = (const float*)d_in[4];
    const float* w_fh   = (const float*)d_in[5];
    const float* b_f    = (const float*)d_in[6];
    const float* w_ox   = (const float*)d_in[7];
    const float* w_oh   = (const float*)d_in[8];
    const float* b_o    = (const float*)d_in[9];
    const float* w_cx   = (const float*)d_in[10];
    const float* w_ch   = (const float*)d_in[11];
    const float* b_c    = (const float*)d_in[12];
    const float* h_last = (const float*)d_in[13];
    const float* c_last = (const float*)d_in[14];
    const float* e_w_ix = (const float*)d_in[15];
    const float* e_w_ih = (const float*)d_in[16];
    const float* e_b_i  = (const float*)d_in[17];
    const float* e_w_fx = (const float*)d_in[18];
    const float* e_w_fh = (const float*)d_in[19];
    const float* e_b_f  = (const float*)d_in[20];
    const float* e_w_cx = (const float*)d_in[21];
    const float* e_w_ch = (const float*)d_in[22];
    const float* e_b_c  = (const float*)d_in[23];
    float* out = (float*)d_out;

    GatePtrs p;
    p.wx[0] = w_ix; p.wx[1] = w_fx; p.wx[2] = w_ox; p.wx[3] = w_cx;
    p.wh[0] = w_ih; p.wh[1] = w_fh; p.wh[2] = w_oh; p.wh[3] = w_ch;

    dim3 g1(HH / 16, 4, 3);
    gates_kernel<<<g1, 128>>>(x, h_last, p);

    point_kernel<<<BH / 256, 256>>>(c_last, b_i, b_f, b_o, b_c,
                                    e_b_i, e_b_f, e_b_c, out);

    dim3 g3(HH / JT, Bb);
    trace_kernel<<<g3, 256>>>(x, h_last, e_w_ix, e_w_ih, e_w_fx, e_w_fh,
                              e_w_cx, e_w_ch, out);
}